// round 4
// baseline (speedup 1.0000x reference)
#include <cuda_runtime.h>
#include <cstdint>
#include <cstddef>

// EncoderRNN: y = GRU(Linear(x)), B=256, T=1024, IN=64, H=256.
// 8-CTA cluster holds fused weights [W_hh | W_ih@W_lin] (768x320 fp32) in smem.
// 512 threads: one (u,q) pair per thread (32 u x 16 q), 3 gate rows each, f32x2 FMA.
// h exchange: stage 32 h_new floats per q, bulk-copy 2304B block to each peer
// (cp.async.bulk.shared::cluster), one mbarrier tx-wait per step, double buffered.

#define BATCH   256
#define TT      1024
#define INDIM   64
#define HH      256
#define CL      8
#define NB      16
#define NU      32
#define NROW    (3*NU)        // 96
#define THREADS 512
#define WSTR    324           // weight row stride (floats); %32==4
#define CHSTR   36            // h row stride (floats); %32==4
#define CHUNK   (NB*CHSTR)    // 576 floats = 2304 B per srcCTA block
#define XSTR    68            // x row stride (floats); %32==4
#define TXB     (CL*CHUNK*4)  // 18432 B per buffer per step

typedef unsigned long long ull;

__device__ __forceinline__ uint32_t smem_u32(const void* p) {
    uint32_t a;
    asm("{ .reg .u64 t; cvta.to.shared.u64 t, %1; cvt.u32.u64 %0, t; }"
        : "=r"(a) : "l"(p));
    return a;
}
__device__ __forceinline__ void ffma2(ull& d, ull a, ull b) {
    asm("fma.rn.f32x2 %0, %1, %2, %0;" : "+l"(d) : "l"(a), "l"(b));
}
__device__ __forceinline__ float hsum2(ull v) {
    float x, y;
    asm("mov.b64 {%0, %1}, %2;" : "=f"(x), "=f"(y) : "l"(v));
    return x + y;
}
__device__ __forceinline__ void dsmem_bulk_cp(uint32_t dst_l, uint32_t src_l,
                                              uint32_t mbar_l, uint32_t rank,
                                              uint32_t bytes) {
    uint32_t rd, rm;
    asm volatile("mapa.shared::cluster.u32 %0, %1, %2;" : "=r"(rd) : "r"(dst_l),  "r"(rank));
    asm volatile("mapa.shared::cluster.u32 %0, %1, %2;" : "=r"(rm) : "r"(mbar_l), "r"(rank));
    asm volatile("cp.async.bulk.shared::cluster.shared::cta.mbarrier::complete_tx::bytes "
                 "[%0], [%1], %2, [%3];"
                 :: "r"(rd), "r"(src_l), "r"(bytes), "r"(rm) : "memory");
}
__device__ __forceinline__ void mbar_init(uint32_t a, uint32_t cnt) {
    asm volatile("mbarrier.init.shared.b64 [%0], %1;" :: "r"(a), "r"(cnt) : "memory");
}
__device__ __forceinline__ void mbar_expect_tx(uint32_t a, uint32_t tx) {
    asm volatile("mbarrier.arrive.expect_tx.shared.b64 _, [%0], %1;" :: "r"(a), "r"(tx) : "memory");
}
__device__ __forceinline__ void mbar_wait(uint32_t a, uint32_t parity) {
    asm volatile("{\n\t.reg .pred P;\n"
                 "W%=:\n\t"
                 "mbarrier.try_wait.parity.acquire.cta.shared::cta.b64 P, [%0], %1, 0x989680;\n\t"
                 "@!P bra W%=;\n\t}"
                 :: "r"(a), "r"(parity) : "memory");
}
__device__ __forceinline__ void fence_async_shared() {
    asm volatile("fence.proxy.async.shared::cta;" ::: "memory");
}
__device__ __forceinline__ void cluster_sync() {
    asm volatile("barrier.cluster.arrive.aligned;" ::: "memory");
    asm volatile("barrier.cluster.wait.aligned;" ::: "memory");
}
__device__ __forceinline__ float sigm(float x) {
    return __fdividef(1.f, 1.f + __expf(-x));
}
__device__ __forceinline__ float tanh_fast(float x) {
    float ax = fabsf(x);
    float e  = __expf(2.f * ax);
    float r  = 1.f - __fdividef(2.f, e + 1.f);
    return copysignf(r, x);
}

extern __shared__ float smem[];

// smem layout (float offsets):
//   waug   [96][324]        @ 0
//   hbuf   [2][8][16][36]   @ 31104
//   xbuf   [2][16][68]      @ 40320
//   stage  [2][16][36]      @ 42496
//   bias_i [96]             @ 43648
//   bias_h [96]             @ 43744
//   mbar   [2] u64          @ 43840
#define OFF_W     0
#define OFF_H     31104
#define OFF_X     40320
#define OFF_ST    42496
#define OFF_BI    43648
#define OFF_BH    43744
#define OFF_MB    43840
#define SMEM_FL   (43840 + 4)

__global__ void __cluster_dims__(CL, 1, 1) __launch_bounds__(THREADS, 1)
gru_fused_kernel(const float* __restrict__ inp,
                 const float* __restrict__ hidden,
                 const float* __restrict__ W_lin,
                 const float* __restrict__ b_lin,
                 const float* __restrict__ W_ih,
                 const float* __restrict__ b_ih,
                 const float* __restrict__ W_hh,
                 const float* __restrict__ b_hh,
                 float* __restrict__ out,
                 int write_hlast)
{
    float* waug   = smem + OFF_W;
    float* hbuf   = smem + OFF_H;
    float* xbuf   = smem + OFF_X;
    float* stage  = smem + OFF_ST;
    float* bias_i = smem + OFF_BI;
    float* bias_h = smem + OFF_BH;

    const int tid = threadIdx.x;
    uint32_t crank;
    asm("mov.u32 %0, %%cluster_ctarank;" : "=r"(crank));
    const int c  = blockIdx.x / CL;
    const int b0 = c * NB;

    const uint32_t mb0 = smem_u32(smem + OFF_MB);
    const uint32_t mb1 = mb0 + 8;

    // ---------------- Prologue ----------------
    if (tid == 0) {
        mbar_init(mb0, 1); mbar_init(mb1, 1);
        mbar_expect_tx(mb0, TXB); mbar_expect_tx(mb1, TXB);
    }
    // W_hh rows for this CTA's 96 gate rows
    for (int f = tid; f < NROW * HH; f += THREADS) {
        int lr = f >> 8, k = f & 255;
        int g = lr >> 5, ul = lr & 31;
        int R = (g << 8) + (int)crank * NU + ul;
        waug[lr * WSTR + k] = W_hh[R * HH + k];
    }
    // W_comb = W_ih @ W_lin into waug[..][256:320]
    {
        int i = tid & 63, lr0 = tid >> 6;       // i in [0,64), lr0 in [0,8)
        for (int jj = 0; jj < 12; jj++) {
            int lr = lr0 + 8 * jj;
            int g = lr >> 5, ul = lr & 31;
            int R = (g << 8) + (int)crank * NU + ul;
            const float4* wih = (const float4*)(W_ih + (size_t)R * HH);
            float s = 0.f;
            #pragma unroll 8
            for (int m4 = 0; m4 < HH / 4; m4++) {
                float4 w = wih[m4];
                int m = m4 << 2;
                s = fmaf(w.x, W_lin[(m + 0) * INDIM + i], s);
                s = fmaf(w.y, W_lin[(m + 1) * INDIM + i], s);
                s = fmaf(w.z, W_lin[(m + 2) * INDIM + i], s);
                s = fmaf(w.w, W_lin[(m + 3) * INDIM + i], s);
            }
            waug[lr * WSTR + HH + i] = s;
        }
    }
    // biases
    if (tid < NROW) {
        int lr = tid, g = lr >> 5, ul = lr & 31;
        int R = (g << 8) + (int)crank * NU + ul;
        float s = b_ih[R];
        for (int m = 0; m < HH; m++) s = fmaf(W_ih[R * HH + m], b_lin[m], s);
        bias_i[lr] = s;
        bias_h[lr] = b_hh[R];
    }
    // h0 into hbuf buffer 0 (chunked layout)
    for (int f = tid; f < NB * HH; f += THREADS) {
        int b = f >> 8, k = f & 255;
        int s = k >> 5, ul = k & 31;
        hbuf[s * CHUNK + b * CHSTR + ul] = hidden[(b0 + b) * HH + k];
    }
    // x(0) into xbuf buffer 0; prefetch x(1). 2 floats per thread.
    float2 xpre;
    const int xbt = tid >> 5;                 // [0,16)
    const int xii = (tid & 31) << 1;          // [0,64) step 2
    {
        const float* xrow = inp + ((size_t)(b0 + xbt) * TT) * INDIM + xii;
        float2 v = *(const float2*)xrow;
        *(float2*)(xbuf + xbt * XSTR + xii) = v;
        xpre = *(const float2*)(xrow + INDIM);
    }
    __syncthreads();
    cluster_sync();   // peers' mbarriers armed before any sends

    // ---------------- Main recurrence ----------------
    // One (u,q) per thread: warp tile = 4 u x 8 q.
    const int lane = tid & 31;
    const int w    = tid >> 5;                // warp id [0,16)
    const int q    = (w & 1) * 8 + (lane & 7);     // batch in cluster [0,16)
    const int u    = (w >> 1) * 4 + (lane >> 3);   // h-unit [0,32)
    const int jglob = (int)crank * NU + u;
    const int bg    = b0 + q;

    const float bi_r = bias_i[u], bi_z = bias_i[NU + u], bi_n = bias_i[2 * NU + u];
    const float bh_r = bias_h[u], bh_z = bias_h[NU + u], bh_n = bias_h[2 * NU + u];

    const ulonglong2* wr2 = (const ulonglong2*)(waug + (0 * NU + u) * WSTR);
    const ulonglong2* wz2 = (const ulonglong2*)(waug + (1 * NU + u) * WSTR);
    const ulonglong2* wn2 = (const ulonglong2*)(waug + (2 * NU + u) * WSTR);

    const uint32_t hbuf_sm  = smem_u32(hbuf);
    const uint32_t stage_sm = smem_u32(stage);
    uint32_t mbs[2] = { mb0, mb1 };
    uint32_t ph[2]  = { 0, 0 };

    for (int t = 0; t < TT; t++) {
        const int p = t & 1;
        float* hb_p = hbuf + p * (CL * CHUNK);
        float* xb_p = xbuf + p * (NB * XSTR);

        ull ar = 0, az = 0, anh = 0, anx = 0;

        // ---- x part first (local, independent of incoming h) ----
        {
            const ulonglong2* xq2 = (const ulonglong2*)(xb_p + q * XSTR);
            #pragma unroll
            for (int kk = 0; kk < 16; kk++) {
                ulonglong2 wr = wr2[64 + kk], wz = wz2[64 + kk], wn = wn2[64 + kk];
                ulonglong2 xv = xq2[kk];
                ffma2(ar, wr.x, xv.x);  ffma2(ar, wr.y, xv.y);
                ffma2(az, wz.x, xv.x);  ffma2(az, wz.y, xv.y);
                ffma2(anx, wn.x, xv.x); ffma2(anx, wn.y, xv.y);
            }
        }

        // ---- wait for incoming h (hidden behind x-part) ----
        if (t > 0) {
            mbar_wait(mbs[p], ph[p]);
            ph[p] ^= 1;
            if (tid == 0) mbar_expect_tx(mbs[p], TXB);   // re-arm for t+2
        }

        // ---- h part (8 source-CTA chunks) ----
        const float* hq = hb_p + q * CHSTR;
        #pragma unroll 2
        for (int s = 0; s < 8; s++) {
            const ulonglong2* h2 = (const ulonglong2*)(hq + s * CHUNK);
            const int kb = s * 8;
            #pragma unroll
            for (int g = 0; g < 8; g++) {
                ulonglong2 wr = wr2[kb + g], wz = wz2[kb + g], wn = wn2[kb + g];
                ulonglong2 hv = h2[g];
                ffma2(ar, wr.x, hv.x);  ffma2(ar, wr.y, hv.y);
                ffma2(az, wz.x, hv.x);  ffma2(az, wz.y, hv.y);
                ffma2(anh, wn.x, hv.x); ffma2(anh, wn.y, hv.y);
            }
        }

        // gates
        float hold = hb_p[crank * CHUNK + q * CHSTR + u];
        float rg = sigm(hsum2(ar) + bi_r + bh_r);
        float zg = sigm(hsum2(az) + bi_z + bh_z);
        float ng = tanh_fast(hsum2(anx) + bi_n + rg * (hsum2(anh) + bh_n));
        float hn = (1.f - zg) * ng + zg * hold;

        // outputs
        out[((size_t)bg * TT + t) * HH + jglob] = hn;
        if (write_hlast && t == TT - 1)
            out[(size_t)BATCH * TT * HH + (size_t)bg * HH + jglob] = hn;

        if (t < TT - 1) {
            // stage h_new locally (bank = 4q+u : conflict-free)
            stage[p * (NB * CHSTR) + q * CHSTR + u] = hn;

            // stage x(t+1) into next buffer
            *(float2*)(xbuf + (1 - p) * (NB * XSTR) + xbt * XSTR + xii) = xpre;
            if (t < TT - 2)
                xpre = *(const float2*)(inp + ((size_t)(b0 + xbt) * TT + (t + 2)) * INDIM + xii);

            __syncthreads();   // staging complete before bulk copies

            // 8 bulk copies: our 2304B block -> each peer's hbuf[1-p] chunk slot
            if (tid < CL) {
                fence_async_shared();
                uint32_t src = stage_sm + (uint32_t)(p * (NB * CHSTR) * 4);
                uint32_t dst = hbuf_sm + (uint32_t)(((1 - p) * (CL * CHUNK) + (int)crank * CHUNK) * 4);
                dsmem_bulk_cp(dst, src, mbs[1 - p], (uint32_t)tid, (uint32_t)(CHUNK * 4));
            }
        }
    }
    cluster_sync();   // no CTA exits while peers may still reference cluster smem

    (void)mb1;
}

extern "C" void kernel_launch(void* const* d_in, const int* in_sizes, int n_in,
                              void* d_out, int out_size) {
    (void)in_sizes; (void)n_in;
    const float* inp    = (const float*)d_in[0];
    const float* hidden = (const float*)d_in[1];
    const float* W_lin  = (const float*)d_in[2];
    const float* b_lin  = (const float*)d_in[3];
    const float* W_ih   = (const float*)d_in[4];
    const float* b_ih   = (const float*)d_in[5];
    const float* W_hh   = (const float*)d_in[6];
    const float* b_hh   = (const float*)d_in[7];

    const int smem_bytes = SMEM_FL * (int)sizeof(float);
    cudaFuncSetAttribute(gru_fused_kernel,
                         cudaFuncAttributeMaxDynamicSharedMemorySize, smem_bytes);

    const int write_hlast = (out_size > BATCH * TT * HH) ? 1 : 0;
    const int grid = (BATCH / NB) * CL;   // 128
    gru_fused_kernel<<<grid, THREADS, smem_bytes>>>(
        inp, hidden, W_lin, b_lin, W_ih, b_ih, W_hh, b_hh,
        (float*)d_out, write_hlast);
}

// round 5
// speedup vs baseline: 1.0005x; 1.0005x over previous
#include <cuda_runtime.h>
#include <cstdint>
#include <cstddef>

// EncoderRNN: y = GRU(Linear(x)), B=256, T=1024, IN=64, H=256.
// 8-CTA cluster holds fused weights [W_hh | W_ih@W_lin] (768x320 fp32) in smem.
// 512 threads: one (u,q) pair per thread (32 u x 16 q), 3 gate rows each, f32x2 FMA.
// h exchange: stage 32 h_new floats per q, bulk-copy 2304B block to each peer
// (cp.async.bulk.shared::cluster), one mbarrier tx-wait per step, double buffered.

#define BATCH   256
#define TT      1024
#define INDIM   64
#define HH      256
#define CL      8
#define NB      16
#define NU      32
#define NROW    (3*NU)        // 96
#define THREADS 512
#define WSTR    324           // weight row stride (floats); %32==4
#define CHSTR   36            // h row stride (floats); %32==4
#define CHUNK   (NB*CHSTR)    // 576 floats = 2304 B per srcCTA block
#define XSTR    68            // x row stride (floats); %32==4
#define TXB     (CL*CHUNK*4)  // 18432 B per buffer per step

typedef unsigned long long ull;

__device__ __forceinline__ uint32_t smem_u32(const void* p) {
    uint32_t a;
    asm("{ .reg .u64 t; cvta.to.shared.u64 t, %1; cvt.u32.u64 %0, t; }"
        : "=r"(a) : "l"(p));
    return a;
}
__device__ __forceinline__ void ffma2(ull& d, ull a, ull b) {
    asm("fma.rn.f32x2 %0, %1, %2, %0;" : "+l"(d) : "l"(a), "l"(b));
}
__device__ __forceinline__ float hsum2(ull v) {
    float x, y;
    asm("mov.b64 {%0, %1}, %2;" : "=f"(x), "=f"(y) : "l"(v));
    return x + y;
}
__device__ __forceinline__ void dsmem_bulk_cp(uint32_t dst_l, uint32_t src_l,
                                              uint32_t mbar_l, uint32_t rank,
                                              uint32_t bytes) {
    uint32_t rd, rm;
    asm volatile("mapa.shared::cluster.u32 %0, %1, %2;" : "=r"(rd) : "r"(dst_l),  "r"(rank));
    asm volatile("mapa.shared::cluster.u32 %0, %1, %2;" : "=r"(rm) : "r"(mbar_l), "r"(rank));
    asm volatile("cp.async.bulk.shared::cluster.shared::cta.mbarrier::complete_tx::bytes "
                 "[%0], [%1], %2, [%3];"
                 :: "r"(rd), "r"(src_l), "r"(bytes), "r"(rm) : "memory");
}
__device__ __forceinline__ void mbar_init(uint32_t a, uint32_t cnt) {
    asm volatile("mbarrier.init.shared.b64 [%0], %1;" :: "r"(a), "r"(cnt) : "memory");
}
__device__ __forceinline__ void mbar_expect_tx(uint32_t a, uint32_t tx) {
    asm volatile("mbarrier.arrive.expect_tx.shared.b64 _, [%0], %1;" :: "r"(a), "r"(tx) : "memory");
}
__device__ __forceinline__ void mbar_wait(uint32_t a, uint32_t parity) {
    asm volatile("{\n\t.reg .pred P;\n"
                 "W%=:\n\t"
                 "mbarrier.try_wait.parity.acquire.cta.shared::cta.b64 P, [%0], %1, 0x989680;\n\t"
                 "@!P bra W%=;\n\t}"
                 :: "r"(a), "r"(parity) : "memory");
}
__device__ __forceinline__ void fence_async_shared() {
    asm volatile("fence.proxy.async.shared::cta;" ::: "memory");
}
__device__ __forceinline__ void cluster_sync() {
    asm volatile("barrier.cluster.arrive.aligned;" ::: "memory");
    asm volatile("barrier.cluster.wait.aligned;" ::: "memory");
}
__device__ __forceinline__ float sigm(float x) {
    return __fdividef(1.f, 1.f + __expf(-x));
}
__device__ __forceinline__ float tanh_fast(float x) {
    float ax = fabsf(x);
    float e  = __expf(2.f * ax);
    float r  = 1.f - __fdividef(2.f, e + 1.f);
    return copysignf(r, x);
}

extern __shared__ float smem[];

// smem layout (float offsets):
//   waug   [96][324]        @ 0
//   hbuf   [2][8][16][36]   @ 31104
//   xbuf   [2][16][68]      @ 40320
//   stage  [2][16][36]      @ 42496
//   bias_i [96]             @ 43648
//   bias_h [96]             @ 43744
//   mbar   [2] u64          @ 43840
#define OFF_W     0
#define OFF_H     31104
#define OFF_X     40320
#define OFF_ST    42496
#define OFF_BI    43648
#define OFF_BH    43744
#define OFF_MB    43840
#define SMEM_FL   (43840 + 4)

__global__ void __cluster_dims__(CL, 1, 1) __launch_bounds__(THREADS, 1)
gru_fused_kernel(const float* __restrict__ inp,
                 const float* __restrict__ hidden,
                 const float* __restrict__ W_lin,
                 const float* __restrict__ b_lin,
                 const float* __restrict__ W_ih,
                 const float* __restrict__ b_ih,
                 const float* __restrict__ W_hh,
                 const float* __restrict__ b_hh,
                 float* __restrict__ out,
                 int write_hlast)
{
    float* waug   = smem + OFF_W;
    float* hbuf   = smem + OFF_H;
    float* xbuf   = smem + OFF_X;
    float* stage  = smem + OFF_ST;
    float* bias_i = smem + OFF_BI;
    float* bias_h = smem + OFF_BH;

    const int tid = threadIdx.x;
    uint32_t crank;
    asm("mov.u32 %0, %%cluster_ctarank;" : "=r"(crank));
    const int c  = blockIdx.x / CL;
    const int b0 = c * NB;

    const uint32_t mb0 = smem_u32(smem + OFF_MB);
    const uint32_t mb1 = mb0 + 8;

    // ---------------- Prologue ----------------
    if (tid == 0) {
        mbar_init(mb0, 1); mbar_init(mb1, 1);
        mbar_expect_tx(mb0, TXB); mbar_expect_tx(mb1, TXB);
    }
    // W_hh rows for this CTA's 96 gate rows
    for (int f = tid; f < NROW * HH; f += THREADS) {
        int lr = f >> 8, k = f & 255;
        int g = lr >> 5, ul = lr & 31;
        int R = (g << 8) + (int)crank * NU + ul;
        waug[lr * WSTR + k] = W_hh[R * HH + k];
    }
    // W_comb = W_ih @ W_lin into waug[..][256:320]
    {
        int i = tid & 63, lr0 = tid >> 6;       // i in [0,64), lr0 in [0,8)
        for (int jj = 0; jj < 12; jj++) {
            int lr = lr0 + 8 * jj;
            int g = lr >> 5, ul = lr & 31;
            int R = (g << 8) + (int)crank * NU + ul;
            const float4* wih = (const float4*)(W_ih + (size_t)R * HH);
            float s = 0.f;
            #pragma unroll 8
            for (int m4 = 0; m4 < HH / 4; m4++) {
                float4 w = wih[m4];
                int m = m4 << 2;
                s = fmaf(w.x, W_lin[(m + 0) * INDIM + i], s);
                s = fmaf(w.y, W_lin[(m + 1) * INDIM + i], s);
                s = fmaf(w.z, W_lin[(m + 2) * INDIM + i], s);
                s = fmaf(w.w, W_lin[(m + 3) * INDIM + i], s);
            }
            waug[lr * WSTR + HH + i] = s;
        }
    }
    // biases
    if (tid < NROW) {
        int lr = tid, g = lr >> 5, ul = lr & 31;
        int R = (g << 8) + (int)crank * NU + ul;
        float s = b_ih[R];
        for (int m = 0; m < HH; m++) s = fmaf(W_ih[R * HH + m], b_lin[m], s);
        bias_i[lr] = s;
        bias_h[lr] = b_hh[R];
    }
    // h0 into hbuf buffer 0 (chunked layout)
    for (int f = tid; f < NB * HH; f += THREADS) {
        int b = f >> 8, k = f & 255;
        int s = k >> 5, ul = k & 31;
        hbuf[s * CHUNK + b * CHSTR + ul] = hidden[(b0 + b) * HH + k];
    }
    // x(0) into xbuf buffer 0; prefetch x(1). 2 floats per thread.
    float2 xpre;
    const int xbt = tid >> 5;                 // [0,16)
    const int xii = (tid & 31) << 1;          // [0,64) step 2
    {
        const float* xrow = inp + ((size_t)(b0 + xbt) * TT) * INDIM + xii;
        float2 v = *(const float2*)xrow;
        *(float2*)(xbuf + xbt * XSTR + xii) = v;
        xpre = *(const float2*)(xrow + INDIM);
    }
    __syncthreads();
    cluster_sync();   // peers' mbarriers armed before any sends

    // ---------------- Main recurrence ----------------
    // One (u,q) per thread: warp tile = 4 u x 8 q.
    const int lane = tid & 31;
    const int w    = tid >> 5;                // warp id [0,16)
    const int q    = (w & 1) * 8 + (lane & 7);     // batch in cluster [0,16)
    const int u    = (w >> 1) * 4 + (lane >> 3);   // h-unit [0,32)
    const int jglob = (int)crank * NU + u;
    const int bg    = b0 + q;

    const float bi_r = bias_i[u], bi_z = bias_i[NU + u], bi_n = bias_i[2 * NU + u];
    const float bh_r = bias_h[u], bh_z = bias_h[NU + u], bh_n = bias_h[2 * NU + u];

    const ulonglong2* wr2 = (const ulonglong2*)(waug + (0 * NU + u) * WSTR);
    const ulonglong2* wz2 = (const ulonglong2*)(waug + (1 * NU + u) * WSTR);
    const ulonglong2* wn2 = (const ulonglong2*)(waug + (2 * NU + u) * WSTR);

    const uint32_t hbuf_sm  = smem_u32(hbuf);
    const uint32_t stage_sm = smem_u32(stage);
    uint32_t mbs[2] = { mb0, mb1 };
    uint32_t ph[2]  = { 0, 0 };

    for (int t = 0; t < TT; t++) {
        const int p = t & 1;
        float* hb_p = hbuf + p * (CL * CHUNK);
        float* xb_p = xbuf + p * (NB * XSTR);

        ull ar = 0, az = 0, anh = 0, anx = 0;

        // ---- x part first (local, independent of incoming h) ----
        {
            const ulonglong2* xq2 = (const ulonglong2*)(xb_p + q * XSTR);
            #pragma unroll
            for (int kk = 0; kk < 16; kk++) {
                ulonglong2 wr = wr2[64 + kk], wz = wz2[64 + kk], wn = wn2[64 + kk];
                ulonglong2 xv = xq2[kk];
                ffma2(ar, wr.x, xv.x);  ffma2(ar, wr.y, xv.y);
                ffma2(az, wz.x, xv.x);  ffma2(az, wz.y, xv.y);
                ffma2(anx, wn.x, xv.x); ffma2(anx, wn.y, xv.y);
            }
        }

        // ---- wait for incoming h (hidden behind x-part) ----
        if (t > 0) {
            mbar_wait(mbs[p], ph[p]);
            ph[p] ^= 1;
            if (tid == 0) mbar_expect_tx(mbs[p], TXB);   // re-arm for t+2
        }

        // ---- h part (8 source-CTA chunks) ----
        const float* hq = hb_p + q * CHSTR;
        #pragma unroll 2
        for (int s = 0; s < 8; s++) {
            const ulonglong2* h2 = (const ulonglong2*)(hq + s * CHUNK);
            const int kb = s * 8;
            #pragma unroll
            for (int g = 0; g < 8; g++) {
                ulonglong2 wr = wr2[kb + g], wz = wz2[kb + g], wn = wn2[kb + g];
                ulonglong2 hv = h2[g];
                ffma2(ar, wr.x, hv.x);  ffma2(ar, wr.y, hv.y);
                ffma2(az, wz.x, hv.x);  ffma2(az, wz.y, hv.y);
                ffma2(anh, wn.x, hv.x); ffma2(anh, wn.y, hv.y);
            }
        }

        // gates
        float hold = hb_p[crank * CHUNK + q * CHSTR + u];
        float rg = sigm(hsum2(ar) + bi_r + bh_r);
        float zg = sigm(hsum2(az) + bi_z + bh_z);
        float ng = tanh_fast(hsum2(anx) + bi_n + rg * (hsum2(anh) + bh_n));
        float hn = (1.f - zg) * ng + zg * hold;

        // outputs
        out[((size_t)bg * TT + t) * HH + jglob] = hn;
        if (write_hlast && t == TT - 1)
            out[(size_t)BATCH * TT * HH + (size_t)bg * HH + jglob] = hn;

        if (t < TT - 1) {
            // stage h_new locally (bank = 4q+u : conflict-free)
            stage[p * (NB * CHSTR) + q * CHSTR + u] = hn;

            // stage x(t+1) into next buffer
            *(float2*)(xbuf + (1 - p) * (NB * XSTR) + xbt * XSTR + xii) = xpre;
            if (t < TT - 2)
                xpre = *(const float2*)(inp + ((size_t)(b0 + xbt) * TT + (t + 2)) * INDIM + xii);

            __syncthreads();   // staging complete before bulk copies

            // 8 bulk copies: our 2304B block -> each peer's hbuf[1-p] chunk slot
            if (tid < CL) {
                fence_async_shared();
                uint32_t src = stage_sm + (uint32_t)(p * (NB * CHSTR) * 4);
                uint32_t dst = hbuf_sm + (uint32_t)(((1 - p) * (CL * CHUNK) + (int)crank * CHUNK) * 4);
                dsmem_bulk_cp(dst, src, mbs[1 - p], (uint32_t)tid, (uint32_t)(CHUNK * 4));
            }
        }
    }
    cluster_sync();   // no CTA exits while peers may still reference cluster smem

    (void)mb1;
}

extern "C" void kernel_launch(void* const* d_in, const int* in_sizes, int n_in,
                              void* d_out, int out_size) {
    (void)in_sizes; (void)n_in;
    const float* inp    = (const float*)d_in[0];
    const float* hidden = (const float*)d_in[1];
    const float* W_lin  = (const float*)d_in[2];
    const float* b_lin  = (const float*)d_in[3];
    const float* W_ih   = (const float*)d_in[4];
    const float* b_ih   = (const float*)d_in[5];
    const float* W_hh   = (const float*)d_in[6];
    const float* b_hh   = (const float*)d_in[7];

    const int smem_bytes = SMEM_FL * (int)sizeof(float);
    cudaFuncSetAttribute(gru_fused_kernel,
                         cudaFuncAttributeMaxDynamicSharedMemorySize, smem_bytes);

    const int write_hlast = (out_size > BATCH * TT * HH) ? 1 : 0;
    const int grid = (BATCH / NB) * CL;   // 128
    gru_fused_kernel<<<grid, THREADS, smem_bytes>>>(
        inp, hidden, W_lin, b_lin, W_ih, b_ih, W_hh, b_hh,
        (float*)d_out, write_hlast);
}